// round 11
// baseline (speedup 1.0000x reference)
#include <cuda_runtime.h>
#include <cuda_fp16.h>
#include <math.h>
#include <stdint.h>

// Problem constants
#define T_TOK 2048        // B*S
#define D_DIM 1024
#define H_DIM 4096
#define E_NUM 8
#define TOPK 2
#define N_SLOTS (T_TOK * TOPK)    // 4096
#define OUT_ELEMS (T_TOK * D_DIM) // 2097152
#define KSPLIT2 4

// ---------------- device scratch (static, allocation-free) ----------------
__device__ int   g_counts[E_NUM];
__device__ int   g_offsets[E_NUM + 1];
__device__ int   g_cursor[E_NUM];
__device__ int   g_slot_tok[N_SLOTS];
__device__ float g_slot_prob[N_SLOTS];
__device__ int   g_tok_slot[T_TOK * TOPK];
__device__ int   g_top_e[T_TOK * TOPK];
__device__ float g_top_p[T_TOK * TOPK];
__device__ float g_probs8[T_TOK * E_NUM];

__device__ __align__(16) __half g_xh[(size_t)T_TOK * D_DIM];
__device__ __align__(16) __half g_W1h[(size_t)E_NUM * H_DIM * D_DIM];
__device__ __align__(16) __half g_W2h[(size_t)E_NUM * D_DIM * H_DIM];
__device__ __align__(16) __half g_Hh[(size_t)N_SLOTS * H_DIM];
__device__ __align__(16) float g_Y[(size_t)KSPLIT2 * N_SLOTS * D_DIM];  // 64 MB

// ---------------- PTX helpers (sm_80-class only; no 'a' features) ----------------
__device__ __forceinline__ uint32_t smem_u32(const void* p) {
    return (uint32_t)__cvta_generic_to_shared(p);
}

__device__ __forceinline__ void cp16(uint32_t saddr, const void* gaddr) {
    asm volatile("cp.async.cg.shared.global [%0], [%1], 16;" :: "r"(saddr), "l"(gaddr));
}
#define CP_COMMIT() asm volatile("cp.async.commit_group;" ::: "memory")
#define CP_WAIT_2() asm volatile("cp.async.wait_group 2;" ::: "memory")

__device__ __forceinline__ void ldsm_x4(uint32_t* r, uint32_t addr) {
    asm volatile("ldmatrix.sync.aligned.m8n8.x4.shared.b16 {%0,%1,%2,%3}, [%4];"
        : "=r"(r[0]), "=r"(r[1]), "=r"(r[2]), "=r"(r[3]) : "r"(addr));
}
__device__ __forceinline__ void ldsm_x2(uint32_t* r, uint32_t addr) {
    asm volatile("ldmatrix.sync.aligned.m8n8.x2.shared.b16 {%0,%1}, [%2];"
        : "=r"(r[0]), "=r"(r[1]) : "r"(addr));
}

__device__ __forceinline__ void mma16816(float* d, const uint32_t* a, const uint32_t* b) {
    asm volatile(
        "mma.sync.aligned.m16n8k16.row.col.f32.f16.f16.f32 "
        "{%0,%1,%2,%3}, {%4,%5,%6,%7}, {%8,%9}, {%0,%1,%2,%3};"
        : "+f"(d[0]), "+f"(d[1]), "+f"(d[2]), "+f"(d[3])
        : "r"(a[0]), "r"(a[1]), "r"(a[2]), "r"(a[3]), "r"(b[0]), "r"(b[1]));
}

// ---------------- init ----------------
__global__ void init_kernel() {
    if (threadIdx.x < E_NUM) g_counts[threadIdx.x] = 0;
}

// ---------------- router ----------------
__global__ void router_kernel(const float* __restrict__ x,
                              const float* __restrict__ Wg) {
    const int t = blockIdx.x;
    const float* xr = x + (size_t)t * D_DIM;
    float acc[E_NUM];
#pragma unroll
    for (int e = 0; e < E_NUM; e++) acc[e] = 0.f;

    for (int d = threadIdx.x; d < D_DIM; d += 128) {
        float xv = xr[d];
#pragma unroll
        for (int e = 0; e < E_NUM; e++)
            acc[e] = fmaf(xv, Wg[e * D_DIM + d], acc[e]);
    }
#pragma unroll
    for (int e = 0; e < E_NUM; e++)
#pragma unroll
        for (int off = 16; off > 0; off >>= 1)
            acc[e] += __shfl_xor_sync(0xffffffffu, acc[e], off);

    __shared__ float s[E_NUM][4];
    const int warp = threadIdx.x >> 5, lane = threadIdx.x & 31;
    if (lane == 0)
#pragma unroll
        for (int e = 0; e < E_NUM; e++) s[e][warp] = acc[e];
    __syncthreads();

    if (threadIdx.x == 0) {
        float lg[E_NUM];
#pragma unroll
        for (int e = 0; e < E_NUM; e++)
            lg[e] = s[e][0] + s[e][1] + s[e][2] + s[e][3];
        float mx = lg[0];
#pragma unroll
        for (int e = 1; e < E_NUM; e++) mx = fmaxf(mx, lg[e]);
        float se = 0.f, pe[E_NUM];
#pragma unroll
        for (int e = 0; e < E_NUM; e++) { pe[e] = expf(lg[e] - mx); se += pe[e]; }
        float inv = 1.f / se;
#pragma unroll
        for (int e = 0; e < E_NUM; e++) g_probs8[t * E_NUM + e] = pe[e] * inv;
        int i1 = 0;
#pragma unroll
        for (int e = 1; e < E_NUM; e++) if (lg[e] > lg[i1]) i1 = e;
        int i2 = -1;
#pragma unroll
        for (int e = 0; e < E_NUM; e++) {
            if (e == i1) continue;
            if (i2 < 0 || lg[e] > lg[i2]) i2 = e;
        }
        float v1 = lg[i1], v2 = lg[i2];
        float m = fmaxf(v1, v2);
        float e1 = expf(v1 - m), e2 = expf(v2 - m);
        float denom = 1.f / (e1 + e2);
        g_top_e[t * 2 + 0] = i1;  g_top_e[t * 2 + 1] = i2;
        g_top_p[t * 2 + 0] = e1 * denom;
        g_top_p[t * 2 + 1] = e2 * denom;
        atomicAdd(&g_counts[i1], 1);
        atomicAdd(&g_counts[i2], 1);
    }
}

// ---------------- finalize: offsets + scatter + aux (one CTA) ----------------
__global__ void finalize_kernel(float* __restrict__ out, int out_size) {
    const int tid = threadIdx.x;   // 1024 threads
    if (tid == 0) {
        int o = 0;
        for (int e = 0; e < E_NUM; e++) {
            g_offsets[e] = o; g_cursor[e] = o; o += g_counts[e];
        }
        g_offsets[E_NUM] = o;
    }
    __syncthreads();

    // scatter
    for (int t = tid; t < T_TOK; t += 1024) {
#pragma unroll
        for (int k = 0; k < TOPK; k++) {
            int e = g_top_e[t * 2 + k];
            int sidx = atomicAdd(&g_cursor[e], 1);
            g_slot_tok[sidx]  = t;
            g_slot_prob[sidx] = g_top_p[t * 2 + k];
            g_tok_slot[t * 2 + k] = sidx;
        }
    }

    // aux loss (deterministic reduction)
    __shared__ float red[E_NUM][1024];
    float ls[E_NUM];
#pragma unroll
    for (int e = 0; e < E_NUM; e++) ls[e] = 0.f;
    for (int t = tid; t < T_TOK; t += 1024)
#pragma unroll
        for (int e = 0; e < E_NUM; e++) ls[e] += g_probs8[t * E_NUM + e];
#pragma unroll
    for (int e = 0; e < E_NUM; e++) red[e][tid] = ls[e];
    __syncthreads();
    for (int st = 512; st > 0; st >>= 1) {
        if (tid < st)
#pragma unroll
            for (int e = 0; e < E_NUM; e++)
                red[e][tid] += red[e][tid + st];
        __syncthreads();
    }
    if (tid == 0 && out_size > OUT_ELEMS) {
        float aux = 0.f;
        for (int e = 0; e < E_NUM; e++)
            aux += (red[e][0] / (float)T_TOK) * ((float)g_counts[e] / (float)T_TOK);
        out[OUT_ELEMS] = (float)E_NUM * aux;
    }
}

// ---------------- fp32 -> fp16 round ----------------
__global__ void round_kernel(const float4* __restrict__ src,
                             uint2* __restrict__ hi, int n4) {
    int i = blockIdx.x * blockDim.x + threadIdx.x;
    int stride = gridDim.x * blockDim.x;
    for (; i < n4; i += stride) {
        float4 v = src[i];
        __half h0 = __float2half_rn(v.x), h1 = __float2half_rn(v.y);
        __half h2 = __float2half_rn(v.z), h3 = __float2half_rn(v.w);
        uint2 hv;
        hv.x = (uint32_t)__half_as_ushort(h0) | ((uint32_t)__half_as_ushort(h1) << 16);
        hv.y = (uint32_t)__half_as_ushort(h2) | ((uint32_t)__half_as_ushort(h3) << 16);
        hi[i] = hv;
    }
}

// ---------------- mma.sync grouped expert GEMM (512 threads, fp16 single-pass) ----
// Block tile BM x BN, 16 warps in WARPS_M x WARPS_N grid, warp tile (BM/WARPS_M)x(BN/WARPS_N).
// K=32 per stage, 4 smem stages, prefetch depth 3, one sync/chunk.
// KS-way split-K: slice kslice handles K range [kslice*K_DIM/KS, ...); partials to
// Y_out + kslice*N_SLOTS*D_DIM; bias added only in slice 0; combine sums slices.

#define KCHUNK 32
#define ROWPAD 40
#define ROWB   (ROWPAD * 2)            // 80 bytes per smem row
#define NSTAGE 4

template <int BM, int BN, int WARPS_M, int WARPS_N, int N_DIM, int K_DIM, int KS, bool FC1>
__global__ void __launch_bounds__(512, 1)
expert_gemm_mma2(const __half* __restrict__ A_g,
                 const __half* __restrict__ B_g,
                 const float* __restrict__ bias,
                 __half* __restrict__ H_out,
                 float* __restrict__ Y_out) {
    constexpr int KSLICE = K_DIM / KS;
    constexpr int NC = KSLICE / KCHUNK;
    constexpr int WTM = BM / WARPS_M;        // warp tile M
    constexpr int WTN = BN / WARPS_N;        // warp tile N
    constexpr int MI = WTM / 16;
    constexpr int NI = WTN / 8;
    constexpr int OFF_A = 0;
    constexpr int OFF_B = BM * ROWB;
    constexpr int ROWS_TOT = BM + BN;
    constexpr int STAGE_B = ROWS_TOT * ROWB;
    constexpr int NJ = (ROWS_TOT + 127) / 128;

    const int e = blockIdx.z;
    const int row_beg = g_offsets[e];
    const int row_end = g_offsets[e + 1];
    const int m0 = row_beg + blockIdx.y * BM;
    if (m0 >= row_end) return;
    constexpr int NXB = N_DIM / BN;
    const int kslice = (KS > 1) ? (blockIdx.x / NXB) : 0;
    const int n0 = (blockIdx.x % NXB) * BN;
    const int kbase = kslice * KSLICE;

    const __half* B_e = B_g + (size_t)e * N_DIM * K_DIM;
    const float* biasE = bias + e * N_DIM;
    float* Yo = Y_out + (size_t)kslice * N_SLOTS * D_DIM;

    extern __shared__ char smem[];
    const uint32_t smb = smem_u32(smem);
    const int tid = threadIdx.x;
    const int wid = tid >> 5;
    const int lane = tid & 31;
    const int warp_m = wid / WARPS_N;
    const int warp_n = wid % WARPS_N;

    // ---- per-thread cp.async sources: NJ rows, one 16B chunk each ----
    const int r0 = tid >> 2;          // 0..127
    const int c16 = tid & 3;          // 16B chunk in row
    const int kc8 = c16 * 8;          // element offset (8 halves per 16B)
    const __half* gsrc[NJ];
    uint32_t sOff[NJ];
#pragma unroll
    for (int j = 0; j < NJ; j++) {
        const int r = r0 + 128 * j;
        if (r >= ROWS_TOT) { gsrc[j] = A_g; sOff[j] = 0; continue; }  // inactive lane-slot
        if (r < BM) {
            int rowg = m0 + r;
            int clr = rowg < row_end ? rowg : (row_end - 1);
            int atok = FC1 ? g_slot_tok[clr] : clr;
            gsrc[j] = A_g + (size_t)atok * K_DIM + kbase + kc8;
            sOff[j] = (uint32_t)(OFF_A + r * ROWB + c16 * 16);
        } else {
            int rb = r - BM;
            gsrc[j] = B_e + (size_t)(n0 + rb) * K_DIM + kbase + kc8;
            sOff[j] = (uint32_t)(OFF_B + rb * ROWB + c16 * 16);
        }
    }

    // ---- ldmatrix per-thread base byte offsets ----
    const int l15 = lane & 15;
    const uint32_t aFrag = (uint32_t)(OFF_A + (warp_m * WTM + l15) * ROWB + (lane >> 4) * 16);
    const uint32_t bFrag = (uint32_t)(OFF_B + (warp_n * WTN + (l15 & 7)) * ROWB + ((l15 >> 3) & 1) * 16);

    float d[MI][NI][4];
#pragma unroll
    for (int mi = 0; mi < MI; mi++)
#pragma unroll
        for (int ni = 0; ni < NI; ni++)
#pragma unroll
            for (int q = 0; q < 4; q++) d[mi][ni][q] = 0.f;

#define ISSUE_STAGE(cidx)                                                          \
    do {                                                                           \
        const uint32_t sb = smb + ((cidx) % NSTAGE) * STAGE_B;                     \
        const int kk = (cidx) * KCHUNK;                                            \
        _Pragma("unroll")                                                          \
        for (int j = 0; j < NJ; j++)                                               \
            if (r0 + 128 * j < ROWS_TOT)                                           \
                cp16(sb + sOff[j], gsrc[j] + kk);                                  \
    } while (0)

    // prologue: 3 stages in flight
    ISSUE_STAGE(0); CP_COMMIT();
    ISSUE_STAGE(1); CP_COMMIT();
    ISSUE_STAGE(2); CP_COMMIT();

    for (int c = 0; c < NC; ++c) {
        CP_WAIT_2();       // stage c resident (uniform: one commit per iteration)
        __syncthreads();   // also guards reuse of buffer (c+3)%4 (read last iter)

        if (c + 3 < NC) ISSUE_STAGE(c + 3);
        CP_COMMIT();

        const uint32_t sb = smb + (c % NSTAGE) * STAGE_B;
        const uint32_t aB = sb + aFrag;
        const uint32_t bB = sb + bFrag;

#pragma unroll
        for (int ks = 0; ks < 2; ks++) {
            uint32_t Af[MI][4], Bf[NI][2];
#pragma unroll
            for (int mi = 0; mi < MI; mi++)
                ldsm_x4(Af[mi], aB + mi * (16 * ROWB) + ks * 32);
#pragma unroll
            for (int ni = 0; ni < NI; ni++)
                ldsm_x2(Bf[ni], bB + ni * (8 * ROWB) + ks * 32);
#pragma unroll
            for (int mi = 0; mi < MI; mi++)
#pragma unroll
                for (int ni = 0; ni < NI; ni++)
                    mma16816(d[mi][ni], Af[mi], Bf[ni]);
        }
    }

    // ---- epilogue ----
    const int rl = lane >> 2;          // 0..7
    const int cl = (lane & 3) * 2;     // 0,2,4,6
    const bool addBias = (kslice == 0);
#pragma unroll
    for (int mi = 0; mi < MI; mi++) {
#pragma unroll
        for (int half = 0; half < 2; half++) {
            const int row = m0 + warp_m * WTM + mi * 16 + rl + half * 8;
            if (row >= row_end) continue;
            if (FC1) {
#pragma unroll
                for (int ni = 0; ni < NI; ni++) {
                    const int col = n0 + warp_n * WTN + ni * 8 + cl;
                    float v0 = fmaxf(d[mi][ni][half * 2 + 0] + biasE[col], 0.f);
                    float v1 = fmaxf(d[mi][ni][half * 2 + 1] + biasE[col + 1], 0.f);
                    __half h0 = __float2half_rn(v0), h1 = __float2half_rn(v1);
                    uint32_t hp = (uint32_t)__half_as_ushort(h0) |
                                  ((uint32_t)__half_as_ushort(h1) << 16);
                    *(uint32_t*)(H_out + (size_t)row * N_DIM + col) = hp;
                }
            } else {
                const float p = g_slot_prob[row];
#pragma unroll
                for (int ni = 0; ni < NI; ni++) {
                    const int col = n0 + warp_n * WTN + ni * 8 + cl;
                    float b0 = addBias ? biasE[col]     : 0.f;
                    float b1 = addBias ? biasE[col + 1] : 0.f;
                    float2 ov;
                    ov.x = (d[mi][ni][half * 2 + 0] + b0) * p;
                    ov.y = (d[mi][ni][half * 2 + 1] + b1) * p;
                    *(float2*)(Yo + (size_t)row * N_DIM + col) = ov;
                }
            }
        }
    }
#undef ISSUE_STAGE
}

#define SMEM_FC1 (NSTAGE * (128 + 128) * ROWB)   // 81920
#define SMEM_FC2 (NSTAGE * (256 + 64) * ROWB)    // 102400

// ---------------- combine: out[t] = sum over 2 slots x KSPLIT2 slices ----------------
__global__ void combine_kernel(float* __restrict__ out) {
    const int t = blockIdx.x;
    const int s0 = g_tok_slot[t * 2 + 0];
    const int s1 = g_tok_slot[t * 2 + 1];
    const int i = threadIdx.x;     // 256 threads, 256 float4 per row
    float4 acc = make_float4(0.f, 0.f, 0.f, 0.f);
#pragma unroll
    for (int ks = 0; ks < KSPLIT2; ks++) {
        const float4* y0 = (const float4*)(g_Y + ((size_t)ks * N_SLOTS + s0) * D_DIM);
        const float4* y1 = (const float4*)(g_Y + ((size_t)ks * N_SLOTS + s1) * D_DIM);
        float4 a = y0[i], b = y1[i];
        acc.x += a.x + b.x; acc.y += a.y + b.y;
        acc.z += a.z + b.z; acc.w += a.w + b.w;
    }
    ((float4*)(out + (size_t)t * D_DIM))[i] = acc;
}

// ---------------- launch ----------------
extern "C" void kernel_launch(void* const* d_in, const int* in_sizes, int n_in,
                              void* d_out, int out_size) {
    const float* x  = (const float*)d_in[0];   // [2,1024,1024]
    const float* Wg = (const float*)d_in[1];   // [8,1024]
    const float* W1 = (const float*)d_in[2];   // [8,4096,1024]
    const float* b1 = (const float*)d_in[3];   // [8,4096]
    const float* W2 = (const float*)d_in[4];   // [8,1024,4096]
    const float* b2 = (const float*)d_in[5];   // [8,1024]
    float* out = (float*)d_out;

    void *p_xh, *p_w1h, *p_w2h, *p_hh, *p_y;
    cudaGetSymbolAddress(&p_xh, g_xh);
    cudaGetSymbolAddress(&p_w1h, g_W1h);
    cudaGetSymbolAddress(&p_w2h, g_W2h);
    cudaGetSymbolAddress(&p_hh, g_Hh);
    cudaGetSymbolAddress(&p_y, g_Y);

    cudaFuncSetAttribute(expert_gemm_mma2<128, 128, 4, 4, H_DIM, D_DIM, 1, true>,
                         cudaFuncAttributeMaxDynamicSharedMemorySize, SMEM_FC1);
    cudaFuncSetAttribute(expert_gemm_mma2<256, 64, 4, 4, D_DIM, H_DIM, KSPLIT2, false>,
                         cudaFuncAttributeMaxDynamicSharedMemorySize, SMEM_FC2);

    init_kernel<<<1, 32>>>();
    router_kernel<<<T_TOK, 128>>>(x, Wg);
    finalize_kernel<<<1, 1024>>>(out, out_size);

    round_kernel<<<512, 256>>>((const float4*)x, (uint2*)p_xh,
                               (int)((size_t)T_TOK * D_DIM / 4));
    round_kernel<<<2048, 256>>>((const float4*)W1, (uint2*)p_w1h,
                                (int)((size_t)E_NUM * H_DIM * D_DIM / 4));
    round_kernel<<<2048, 256>>>((const float4*)W2, (uint2*)p_w2h,
                                (int)((size_t)E_NUM * D_DIM * H_DIM / 4));

    // fc1: x[gathered] @ W1^T -> relu -> Hh   (tile 128x128, ~1024 active CTAs)
    {
        dim3 grid(H_DIM / 128, T_TOK / 128, E_NUM);
        expert_gemm_mma2<128, 128, 4, 4, H_DIM, D_DIM, 1, true><<<grid, 512, SMEM_FC1>>>(
            (const __half*)p_xh, (const __half*)p_w1h, b1, (__half*)p_hh, nullptr);
    }
    // fc2: H @ W2^T -> *prob -> Y partials  (tile 256x64, split-K=4, ~1024 active CTAs)
    {
        dim3 grid((D_DIM / 64) * KSPLIT2, T_TOK / 256, E_NUM);
        expert_gemm_mma2<256, 64, 4, 4, D_DIM, H_DIM, KSPLIT2, false><<<grid, 512, SMEM_FC2>>>(
            (const __half*)p_hh, (const __half*)p_w2h, b2, nullptr, (float*)p_y);
    }
    combine_kernel<<<T_TOK, 256>>>(out);
}

// round 12
// speedup vs baseline: 1.5036x; 1.5036x over previous
#include <cuda_runtime.h>
#include <cuda_fp16.h>
#include <math.h>
#include <stdint.h>

// Problem constants
#define T_TOK 2048        // B*S
#define D_DIM 1024
#define H_DIM 4096
#define E_NUM 8
#define TOPK 2
#define N_SLOTS (T_TOK * TOPK)    // 4096
#define OUT_ELEMS (T_TOK * D_DIM) // 2097152

// ---------------- device scratch (static, allocation-free) ----------------
__device__ int   g_counts[E_NUM];
__device__ int   g_offsets[E_NUM + 1];
__device__ int   g_cursor[E_NUM];
__device__ int   g_slot_tok[N_SLOTS];
__device__ float g_slot_prob[N_SLOTS];
__device__ int   g_tok_slot[T_TOK * TOPK];
__device__ int   g_top_e[T_TOK * TOPK];
__device__ float g_top_p[T_TOK * TOPK];
__device__ float g_probs8[T_TOK * E_NUM];

__device__ __align__(16) __half g_xh[(size_t)T_TOK * D_DIM];
__device__ __align__(16) __half g_W1h[(size_t)E_NUM * H_DIM * D_DIM];
__device__ __align__(16) __half g_W2h[(size_t)E_NUM * D_DIM * H_DIM];
__device__ __align__(16) __half g_Hh[(size_t)N_SLOTS * H_DIM];
__device__ __align__(16) float g_Y[(size_t)N_SLOTS * D_DIM];

// ---------------- PTX helpers (sm_80-class only; no 'a' features) ----------------
__device__ __forceinline__ uint32_t smem_u32(const void* p) {
    return (uint32_t)__cvta_generic_to_shared(p);
}

__device__ __forceinline__ void cp16(uint32_t saddr, const void* gaddr) {
    asm volatile("cp.async.cg.shared.global [%0], [%1], 16;" :: "r"(saddr), "l"(gaddr));
}
#define CP_COMMIT() asm volatile("cp.async.commit_group;" ::: "memory")
#define CP_WAIT_2() asm volatile("cp.async.wait_group 2;" ::: "memory")

__device__ __forceinline__ void ldsm_x4(uint32_t* r, uint32_t addr) {
    asm volatile("ldmatrix.sync.aligned.m8n8.x4.shared.b16 {%0,%1,%2,%3}, [%4];"
        : "=r"(r[0]), "=r"(r[1]), "=r"(r[2]), "=r"(r[3]) : "r"(addr));
}
__device__ __forceinline__ void ldsm_x2(uint32_t* r, uint32_t addr) {
    asm volatile("ldmatrix.sync.aligned.m8n8.x2.shared.b16 {%0,%1}, [%2];"
        : "=r"(r[0]), "=r"(r[1]) : "r"(addr));
}

__device__ __forceinline__ void mma16816(float* d, const uint32_t* a, const uint32_t* b) {
    asm volatile(
        "mma.sync.aligned.m16n8k16.row.col.f32.f16.f16.f32 "
        "{%0,%1,%2,%3}, {%4,%5,%6,%7}, {%8,%9}, {%0,%1,%2,%3};"
        : "+f"(d[0]), "+f"(d[1]), "+f"(d[2]), "+f"(d[3])
        : "r"(a[0]), "r"(a[1]), "r"(a[2]), "r"(a[3]), "r"(b[0]), "r"(b[1]));
}

// ---------------- init ----------------
__global__ void init_kernel() {
    if (threadIdx.x < E_NUM) g_counts[threadIdx.x] = 0;
}

// ---------------- router ----------------
__global__ void router_kernel(const float* __restrict__ x,
                              const float* __restrict__ Wg) {
    const int t = blockIdx.x;
    const float* xr = x + (size_t)t * D_DIM;
    float acc[E_NUM];
#pragma unroll
    for (int e = 0; e < E_NUM; e++) acc[e] = 0.f;

    for (int d = threadIdx.x; d < D_DIM; d += 128) {
        float xv = xr[d];
#pragma unroll
        for (int e = 0; e < E_NUM; e++)
            acc[e] = fmaf(xv, Wg[e * D_DIM + d], acc[e]);
    }
#pragma unroll
    for (int e = 0; e < E_NUM; e++)
#pragma unroll
        for (int off = 16; off > 0; off >>= 1)
            acc[e] += __shfl_xor_sync(0xffffffffu, acc[e], off);

    __shared__ float s[E_NUM][4];
    const int warp = threadIdx.x >> 5, lane = threadIdx.x & 31;
    if (lane == 0)
#pragma unroll
        for (int e = 0; e < E_NUM; e++) s[e][warp] = acc[e];
    __syncthreads();

    if (threadIdx.x == 0) {
        float lg[E_NUM];
#pragma unroll
        for (int e = 0; e < E_NUM; e++)
            lg[e] = s[e][0] + s[e][1] + s[e][2] + s[e][3];
        float mx = lg[0];
#pragma unroll
        for (int e = 1; e < E_NUM; e++) mx = fmaxf(mx, lg[e]);
        float se = 0.f, pe[E_NUM];
#pragma unroll
        for (int e = 0; e < E_NUM; e++) { pe[e] = expf(lg[e] - mx); se += pe[e]; }
        float inv = 1.f / se;
#pragma unroll
        for (int e = 0; e < E_NUM; e++) g_probs8[t * E_NUM + e] = pe[e] * inv;
        int i1 = 0;
#pragma unroll
        for (int e = 1; e < E_NUM; e++) if (lg[e] > lg[i1]) i1 = e;
        int i2 = -1;
#pragma unroll
        for (int e = 0; e < E_NUM; e++) {
            if (e == i1) continue;
            if (i2 < 0 || lg[e] > lg[i2]) i2 = e;
        }
        float v1 = lg[i1], v2 = lg[i2];
        float m = fmaxf(v1, v2);
        float e1 = expf(v1 - m), e2 = expf(v2 - m);
        float denom = 1.f / (e1 + e2);
        g_top_e[t * 2 + 0] = i1;  g_top_e[t * 2 + 1] = i2;
        g_top_p[t * 2 + 0] = e1 * denom;
        g_top_p[t * 2 + 1] = e2 * denom;
        atomicAdd(&g_counts[i1], 1);
        atomicAdd(&g_counts[i2], 1);
    }
}

// ---------------- finalize: offsets + scatter + aux (one CTA) ----------------
__global__ void finalize_kernel(float* __restrict__ out, int out_size) {
    const int tid = threadIdx.x;   // 1024 threads
    if (tid == 0) {
        int o = 0;
        for (int e = 0; e < E_NUM; e++) {
            g_offsets[e] = o; g_cursor[e] = o; o += g_counts[e];
        }
        g_offsets[E_NUM] = o;
    }
    __syncthreads();

    for (int t = tid; t < T_TOK; t += 1024) {
#pragma unroll
        for (int k = 0; k < TOPK; k++) {
            int e = g_top_e[t * 2 + k];
            int sidx = atomicAdd(&g_cursor[e], 1);
            g_slot_tok[sidx]  = t;
            g_slot_prob[sidx] = g_top_p[t * 2 + k];
            g_tok_slot[t * 2 + k] = sidx;
        }
    }

    __shared__ float red[E_NUM][1024];
    float ls[E_NUM];
#pragma unroll
    for (int e = 0; e < E_NUM; e++) ls[e] = 0.f;
    for (int t = tid; t < T_TOK; t += 1024)
#pragma unroll
        for (int e = 0; e < E_NUM; e++) ls[e] += g_probs8[t * E_NUM + e];
#pragma unroll
    for (int e = 0; e < E_NUM; e++) red[e][tid] = ls[e];
    __syncthreads();
    for (int st = 512; st > 0; st >>= 1) {
        if (tid < st)
#pragma unroll
            for (int e = 0; e < E_NUM; e++)
                red[e][tid] += red[e][tid + st];
        __syncthreads();
    }
    if (tid == 0 && out_size > OUT_ELEMS) {
        float aux = 0.f;
        for (int e = 0; e < E_NUM; e++)
            aux += (red[e][0] / (float)T_TOK) * ((float)g_counts[e] / (float)T_TOK);
        out[OUT_ELEMS] = (float)E_NUM * aux;
    }
}

// ---------------- fp32 -> fp16 round (wide: 8 floats -> 1 uint4 store) ------
__global__ void round_kernel(const float4* __restrict__ src,
                             uint4* __restrict__ dst, int n8) {
    int i = blockIdx.x * blockDim.x + threadIdx.x;
    int stride = gridDim.x * blockDim.x;
    for (; i < n8; i += stride) {
        float4 v0 = src[2 * i];
        float4 v1 = src[2 * i + 1];
        uint4 o;
        o.x = (uint32_t)__half_as_ushort(__float2half_rn(v0.x)) |
              ((uint32_t)__half_as_ushort(__float2half_rn(v0.y)) << 16);
        o.y = (uint32_t)__half_as_ushort(__float2half_rn(v0.z)) |
              ((uint32_t)__half_as_ushort(__float2half_rn(v0.w)) << 16);
        o.z = (uint32_t)__half_as_ushort(__float2half_rn(v1.x)) |
              ((uint32_t)__half_as_ushort(__float2half_rn(v1.y)) << 16);
        o.w = (uint32_t)__half_as_ushort(__float2half_rn(v1.z)) |
              ((uint32_t)__half_as_ushort(__float2half_rn(v1.w)) << 16);
        dst[i] = o;
    }
}

// ---------------- mma.sync grouped expert GEMM (256 threads, fp16) ----------
// Block tile 128x128, 8 warps in 2x4 grid, warp tile 64x32 (proven shape).
// __launch_bounds__(256, 2): 2 CTAs/SM co-resident -> 4 warps/SMSP chip-wide,
// fine CTA granularity for wave balance.
// K=32 per stage, 4 smem stages, prefetch depth 3, one sync/chunk.

#define KCHUNK 32
#define ROWPAD 40
#define ROWB   (ROWPAD * 2)            // 80 bytes per smem row
#define NSTAGE 4
#define BM 128
#define BN 128

template <int N_DIM, int K_DIM, bool FC1>
__global__ void __launch_bounds__(256, 2)
expert_gemm_mma3(const __half* __restrict__ A_g,
                 const __half* __restrict__ B_g,
                 const float* __restrict__ bias,
                 __half* __restrict__ H_out,
                 float* __restrict__ Y_out) {
    constexpr int NC = K_DIM / KCHUNK;
    constexpr int OFF_A = 0;
    constexpr int OFF_B = BM * ROWB;
    constexpr int ROWS_TOT = BM + BN;       // 256
    constexpr int STAGE_B = ROWS_TOT * ROWB;
    constexpr int NJ = 4;                   // 1024 chunks / 256 threads

    const int e = blockIdx.z;
    const int row_beg = g_offsets[e];
    const int row_end = g_offsets[e + 1];
    const int m0 = row_beg + blockIdx.y * BM;
    if (m0 >= row_end) return;
    const int n0 = blockIdx.x * BN;

    const __half* B_e = B_g + (size_t)e * N_DIM * K_DIM;
    const float* biasE = bias + e * N_DIM;

    extern __shared__ char smem[];
    const uint32_t smb = smem_u32(smem);
    const int tid = threadIdx.x;
    const int wid = tid >> 5;
    const int lane = tid & 31;
    const int warp_m = wid >> 2;   // 0..1  (64-row slice)
    const int warp_n = wid & 3;    // 0..3  (32-col slice)

    // ---- per-thread cp.async sources: 4 chunks (chunk id = tid + 256j) ----
    const __half* gsrc[NJ];
    uint32_t sOff[NJ];
#pragma unroll
    for (int j = 0; j < NJ; j++) {
        const int cidx = tid + 256 * j;     // 0..1023
        const int r = cidx >> 2;            // 0..255
        const int c16 = cidx & 3;
        const int kc8 = c16 * 8;
        if (r < BM) {
            int rowg = m0 + r;
            int clr = rowg < row_end ? rowg : (row_end - 1);
            int atok = FC1 ? g_slot_tok[clr] : clr;
            gsrc[j] = A_g + (size_t)atok * K_DIM + kc8;
            sOff[j] = (uint32_t)(OFF_A + r * ROWB + c16 * 16);
        } else {
            int rb = r - BM;
            gsrc[j] = B_e + (size_t)(n0 + rb) * K_DIM + kc8;
            sOff[j] = (uint32_t)(OFF_B + rb * ROWB + c16 * 16);
        }
    }

    // ---- ldmatrix per-thread base byte offsets ----
    const int l15 = lane & 15;
    const uint32_t aFrag = (uint32_t)(OFF_A + (warp_m * 64 + l15) * ROWB + (lane >> 4) * 16);
    const uint32_t bFrag = (uint32_t)(OFF_B + (warp_n * 32 + (l15 & 7)) * ROWB + ((l15 >> 3) & 1) * 16);

    float d[4][4][4];
#pragma unroll
    for (int mi = 0; mi < 4; mi++)
#pragma unroll
        for (int ni = 0; ni < 4; ni++)
#pragma unroll
            for (int q = 0; q < 4; q++) d[mi][ni][q] = 0.f;

#define ISSUE_STAGE(cidx2)                                                         \
    do {                                                                           \
        const uint32_t sb = smb + ((cidx2) % NSTAGE) * STAGE_B;                    \
        const int kk = (cidx2) * KCHUNK;                                           \
        _Pragma("unroll")                                                          \
        for (int j = 0; j < NJ; j++)                                               \
            cp16(sb + sOff[j], gsrc[j] + kk);                                      \
    } while (0)

    // prologue: 3 stages in flight
    ISSUE_STAGE(0); CP_COMMIT();
    ISSUE_STAGE(1); CP_COMMIT();
    ISSUE_STAGE(2); CP_COMMIT();

    for (int c = 0; c < NC; ++c) {
        CP_WAIT_2();       // stage c resident (uniform: one commit per iteration)
        __syncthreads();   // also guards reuse of buffer (c+3)%4 (read last iter)

        if (c + 3 < NC) ISSUE_STAGE(c + 3);
        CP_COMMIT();

        const uint32_t sb = smb + (c % NSTAGE) * STAGE_B;
        const uint32_t aB = sb + aFrag;
        const uint32_t bB = sb + bFrag;

#pragma unroll
        for (int ks = 0; ks < 2; ks++) {
            uint32_t Af[4][4], Bf[4][2];
#pragma unroll
            for (int mi = 0; mi < 4; mi++)
                ldsm_x4(Af[mi], aB + mi * (16 * ROWB) + ks * 32);
#pragma unroll
            for (int ni = 0; ni < 4; ni++)
                ldsm_x2(Bf[ni], bB + ni * (8 * ROWB) + ks * 32);
#pragma unroll
            for (int mi = 0; mi < 4; mi++)
#pragma unroll
                for (int ni = 0; ni < 4; ni++)
                    mma16816(d[mi][ni], Af[mi], Bf[ni]);
        }
    }

    // ---- epilogue ----
    const int rl = lane >> 2;          // 0..7
    const int cl = (lane & 3) * 2;     // 0,2,4,6
#pragma unroll
    for (int mi = 0; mi < 4; mi++) {
#pragma unroll
        for (int half = 0; half < 2; half++) {
            const int row = m0 + warp_m * 64 + mi * 16 + rl + half * 8;
            if (row >= row_end) continue;
            if (FC1) {
#pragma unroll
                for (int ni = 0; ni < 4; ni++) {
                    const int col = n0 + warp_n * 32 + ni * 8 + cl;
                    float v0 = fmaxf(d[mi][ni][half * 2 + 0] + biasE[col], 0.f);
                    float v1 = fmaxf(d[mi][ni][half * 2 + 1] + biasE[col + 1], 0.f);
                    __half h0 = __float2half_rn(v0), h1 = __float2half_rn(v1);
                    uint32_t hp = (uint32_t)__half_as_ushort(h0) |
                                  ((uint32_t)__half_as_ushort(h1) << 16);
                    *(uint32_t*)(H_out + (size_t)row * N_DIM + col) = hp;
                }
            } else {
                const float p = g_slot_prob[row];
#pragma unroll
                for (int ni = 0; ni < 4; ni++) {
                    const int col = n0 + warp_n * 32 + ni * 8 + cl;
                    float2 ov;
                    ov.x = (d[mi][ni][half * 2 + 0] + biasE[col])     * p;
                    ov.y = (d[mi][ni][half * 2 + 1] + biasE[col + 1]) * p;
                    *(float2*)(Y_out + (size_t)row * N_DIM + col) = ov;
                }
            }
        }
    }
#undef ISSUE_STAGE
}

#define SMEM_GEMM (NSTAGE * (BM + BN) * ROWB)   // 81920

// ---------------- combine ----------------
__global__ void combine_kernel(float* __restrict__ out) {
    const int t = blockIdx.x;
    const int s0 = g_tok_slot[t * 2 + 0];
    const int s1 = g_tok_slot[t * 2 + 1];
    const float4* y0 = (const float4*)(g_Y + (size_t)s0 * D_DIM);
    const float4* y1 = (const float4*)(g_Y + (size_t)s1 * D_DIM);
    float4* o = (float4*)(out + (size_t)t * D_DIM);
    int i = threadIdx.x;
    float4 a = y0[i], b = y1[i];
    o[i] = make_float4(a.x + b.x, a.y + b.y, a.z + b.z, a.w + b.w);
}

// ---------------- launch ----------------
extern "C" void kernel_launch(void* const* d_in, const int* in_sizes, int n_in,
                              void* d_out, int out_size) {
    const float* x  = (const float*)d_in[0];   // [2,1024,1024]
    const float* Wg = (const float*)d_in[1];   // [8,1024]
    const float* W1 = (const float*)d_in[2];   // [8,4096,1024]
    const float* b1 = (const float*)d_in[3];   // [8,4096]
    const float* W2 = (const float*)d_in[4];   // [8,1024,4096]
    const float* b2 = (const float*)d_in[5];   // [8,1024]
    float* out = (float*)d_out;

    void *p_xh, *p_w1h, *p_w2h, *p_hh, *p_y;
    cudaGetSymbolAddress(&p_xh, g_xh);
    cudaGetSymbolAddress(&p_w1h, g_W1h);
    cudaGetSymbolAddress(&p_w2h, g_W2h);
    cudaGetSymbolAddress(&p_hh, g_Hh);
    cudaGetSymbolAddress(&p_y, g_Y);

    cudaFuncSetAttribute(expert_gemm_mma3<H_DIM, D_DIM, true>,
                         cudaFuncAttributeMaxDynamicSharedMemorySize, SMEM_GEMM);
    cudaFuncSetAttribute(expert_gemm_mma3<D_DIM, H_DIM, false>,
                         cudaFuncAttributeMaxDynamicSharedMemorySize, SMEM_GEMM);

    init_kernel<<<1, 32>>>();
    router_kernel<<<T_TOK, 128>>>(x, Wg);
    finalize_kernel<<<1, 1024>>>(out, out_size);

    round_kernel<<<256, 256>>>((const float4*)x, (uint4*)p_xh,
                               (int)((size_t)T_TOK * D_DIM / 8));
    round_kernel<<<2048, 256>>>((const float4*)W1, (uint4*)p_w1h,
                                (int)((size_t)E_NUM * H_DIM * D_DIM / 8));
    round_kernel<<<2048, 256>>>((const float4*)W2, (uint4*)p_w2h,
                                (int)((size_t)E_NUM * D_DIM * H_DIM / 8));

    // fc1: x[gathered] @ W1^T -> relu -> Hh   (tile 128x128, ~1024 active CTAs)
    {
        dim3 grid(H_DIM / 128, T_TOK / 128, E_NUM);
        expert_gemm_mma3<H_DIM, D_DIM, true><<<grid, 256, SMEM_GEMM>>>(
            (const __half*)p_xh, (const __half*)p_w1h, b1, (__half*)p_hh, nullptr);
    }
    // fc2: H @ W2^T -> *prob -> Y   (tile 128x128, ~256 active CTAs, 2/SM)
    {
        dim3 grid(D_DIM / 128, T_TOK / 128, E_NUM);
        expert_gemm_mma3<D_DIM, H_DIM, false><<<grid, 256, SMEM_GEMM>>>(
            (const __half*)p_hh, (const __half*)p_w2h, b2, nullptr, (float*)p_y);
    }
    combine_kernel<<<T_TOK, 256>>>(out);
}